// round 15
// baseline (speedup 1.0000x reference)
#include <cuda_runtime.h>
#include <cuda_bf16.h>
#include <cuda_fp16.h>
#include <cstdint>

#define BB 4
#define TT 2048
#define HH 8
#define FF 512
#define MM (BB*TT)   // 8192
#define NZ 4         // key-split factor

// ---------------------------------------------------------------------------
// Global scratch (device globals; uint4 for 16B alignment)
// ---------------------------------------------------------------------------
__device__ uint4 g_qh_[1048576];   // q_cat fp16: [bh=32][t=2048][128] (scaled 0.125, biases fused)
__device__ uint4 g_kh_[1048576];   // k_cat fp16: [bh][t][0:64]=k, [64:128]=p
__device__ uint4 g_vh_[524288];    // V fp16: [bh][t][64]
__device__ uint4 g_xh_[524288];    // x fp16 [8192][512] (single term)
__device__ uint4 g_peh_[131072];   // pos_emb hi fp16 [2048][512]
__device__ uint4 g_pel_[131072];   // pos_emb lo fp16
__device__ uint4 g_wh_[163840];    // 5 weights fp16 [5][512][512] (Wq,Wk,Wv,Wpos,Wout)
__device__ uint4 g_aoh_[524288];   // attention-out fp16 [8192][512] (single term)
__device__ float g_po[(size_t)NZ*MM*FF];  // partial O per z, unnormalized
__device__ float g_ls[NZ*32*TT];          // partial row sums
__device__ float g_lm[NZ*32*TT];          // partial row maxes

#define G_QH ((__half*)g_qh_)
#define G_KH ((__half*)g_kh_)
#define G_VH ((__half*)g_vh_)

// ---------------------------------------------------------------------------
__device__ __forceinline__ uint32_t cvta_s(const void* p) {
    return (uint32_t)__cvta_generic_to_shared(p);
}
__device__ __forceinline__ float ex2f(float x) {
    float r; asm("ex2.approx.ftz.f32 %0, %1;" : "=f"(r) : "f"(x)); return r;
}
// pack two f32 -> f16x2 word: first arg -> low half, second -> high half
__device__ __forceinline__ uint32_t pack2h(float lo, float hi) {
    uint32_t r; asm("cvt.rn.f16x2.f32 %0, %1, %2;" : "=r"(r) : "f"(hi), "f"(lo)); return r;
}

__device__ __forceinline__ void ldsm4(uint32_t r[4], uint32_t a) {
    asm volatile("ldmatrix.sync.aligned.m8n8.x4.shared.b16 {%0,%1,%2,%3}, [%4];"
                 : "=r"(r[0]), "=r"(r[1]), "=r"(r[2]), "=r"(r[3]) : "r"(a));
}
__device__ __forceinline__ void ldsm4t(uint32_t r[4], uint32_t a) {
    asm volatile("ldmatrix.sync.aligned.m8n8.x4.trans.shared.b16 {%0,%1,%2,%3}, [%4];"
                 : "=r"(r[0]), "=r"(r[1]), "=r"(r[2]), "=r"(r[3]) : "r"(a));
}
// fp16 mma, f32 accumulate. Non-volatile: pure register op.
__device__ __forceinline__ void mma16(float c[4], const uint32_t a[4], uint32_t b0, uint32_t b1) {
    asm("mma.sync.aligned.m16n8k16.row.col.f32.f16.f16.f32 "
        "{%0,%1,%2,%3}, {%4,%5,%6,%7}, {%8,%9}, {%0,%1,%2,%3};"
        : "+f"(c[0]), "+f"(c[1]), "+f"(c[2]), "+f"(c[3])
        : "r"(a[0]), "r"(a[1]), "r"(a[2]), "r"(a[3]), "r"(b0), "r"(b1));
}

__device__ __forceinline__ void cpa16(uint32_t d, const void* s) {
    asm volatile("cp.async.cg.shared.global [%0], [%1], 16;" :: "r"(d), "l"(s) : "memory");
}
#define CPA_COMMIT() asm volatile("cp.async.commit_group;" ::: "memory")
#define CPA_WAIT1()  asm volatile("cp.async.wait_group 1;" ::: "memory")
#define CPA_WAIT0()  asm volatile("cp.async.wait_group 0;" ::: "memory")

// wait_group with a literal immediate per case; branch resolves statically
// inside fully-unrolled loops (fixes the R14 "n"-constraint build break).
__device__ __forceinline__ void cpa_wait_dyn(int n) {
    switch (n) {
    case 0: asm volatile("cp.async.wait_group 0;" ::: "memory"); break;
    case 1: asm volatile("cp.async.wait_group 1;" ::: "memory"); break;
    case 2: asm volatile("cp.async.wait_group 2;" ::: "memory"); break;
    case 3: asm volatile("cp.async.wait_group 3;" ::: "memory"); break;
    case 4: asm volatile("cp.async.wait_group 4;" ::: "memory"); break;
    case 5: asm volatile("cp.async.wait_group 5;" ::: "memory"); break;
    case 6: asm volatile("cp.async.wait_group 6;" ::: "memory"); break;
    default: asm volatile("cp.async.wait_group 7;" ::: "memory"); break;
    }
}

#define LOG2E_F 1.4426950408889634f

// ---------------------------------------------------------------------------
// conv_kernel: fp32 -> fp16 conversions. (unchanged)
// ---------------------------------------------------------------------------
__global__ __launch_bounds__(256) void conv_kernel(
    const float* __restrict__ x, const float* __restrict__ pe,
    const float* __restrict__ Wq, const float* __restrict__ Wk,
    const float* __restrict__ Wv, const float* __restrict__ Wpos,
    const float* __restrict__ Wout)
{
    int z = blockIdx.y;
    int stride = gridDim.x * 256;
    if (z == 0) {
        const float4* src = (const float4*)x;
        uint2* dh = (uint2*)g_xh_;
        for (int i = blockIdx.x * 256 + threadIdx.x; i < 1048576; i += stride) {
            float4 v = src[i];
            dh[i] = make_uint2(pack2h(v.x, v.y), pack2h(v.z, v.w));
        }
    } else if (z == 1) {
        const float4* src = (const float4*)pe;
        uint2* dh = (uint2*)g_peh_;
        uint2* dl = (uint2*)g_pel_;
        for (int i = blockIdx.x * 256 + threadIdx.x; i < 262144; i += stride) {
            float4 v = src[i];
            uint32_t h0 = pack2h(v.x, v.y);
            uint32_t h1 = pack2h(v.z, v.w);
            float2 f0 = __half22float2(*reinterpret_cast<__half2*>(&h0));
            float2 f1 = __half22float2(*reinterpret_cast<__half2*>(&h1));
            dh[i] = make_uint2(h0, h1);
            dl[i] = make_uint2(pack2h(v.x - f0.x, v.y - f0.y), pack2h(v.z - f1.x, v.w - f1.y));
        }
    } else {
        int widx = z - 2;
        const float* Wsel = (widx == 0) ? Wq : (widx == 1) ? Wk : (widx == 2) ? Wv
                          : (widx == 3) ? Wpos : Wout;
        const float4* src = (const float4*)Wsel;
        uint2* dh = (uint2*)g_wh_ + (size_t)widx * 65536;
        for (int i = blockIdx.x * 256 + threadIdx.x; i < 65536; i += stride) {
            float4 v = src[i];
            dh[i] = make_uint2(pack2h(v.x, v.y), pack2h(v.z, v.w));
        }
    }
}

// ---------------------------------------------------------------------------
// fp16 tensor-core projection GEMM v2: A fragments loaded DIRECTLY from
// global (no A smem round-trip); all 8 B chunks staged into smem once.
// CTA: 128 rows x 64 cols, 8 warps. K=512 in 8 chunks of 64.
// mode (blockIdx.z if arg<0): 0=Q, 1=K, 2=V, 3=P, 4=OUT — scatter epilogues.
// Only mode 3 (P) adds the pe-lo correction term (loaded at use time).
// ---------------------------------------------------------------------------
#define KSTR2 144              // 64 f16 + 16B pad
#define BCH   (64 * KSTR2)     // 9216 bytes per B chunk
#define GEMM_SMEM (8 * BCH)    // 73728 -> 2 CTAs/SM

// Load one 64-k chunk of A fragments directly from global fp16 (row-major, ld=512).
// Canonical m16n8k16 A layout: reg0=(r, 2c), reg1=(r+8, 2c), reg2=(r, 2c+8), reg3=(r+8, 2c+8).
__device__ __forceinline__ void load_a_chunk(
    uint32_t Af[4][4], const __half* __restrict__ A, int mrow, int k, int l)
{
    int gr = l >> 2, tg = (l & 3) << 1;
    const __half* b0 = A + (size_t)(mrow + gr) * FF + k + tg;
    const __half* b1 = b0 + (size_t)8 * FF;
#pragma unroll
    for (int ks = 0; ks < 4; ks++) {
        Af[ks][0] = *(const uint32_t*)(b0 + ks * 16);
        Af[ks][1] = *(const uint32_t*)(b1 + ks * 16);
        Af[ks][2] = *(const uint32_t*)(b0 + ks * 16 + 8);
        Af[ks][3] = *(const uint32_t*)(b1 + ks * 16 + 8);
    }
}

__global__ __launch_bounds__(256, 2) void proj_kernel(
    int mode_arg, float* __restrict__ out,
    const float* __restrict__ bq, const float* __restrict__ bk,
    const float* __restrict__ bv, const float* __restrict__ bout,
    const float* __restrict__ pbu, const float* __restrict__ pbv)
{
    extern __shared__ char sm[];
    uint32_t sb = cvta_s(sm);

    int tid = threadIdx.x;
    int w = tid >> 5, l = tid & 31;
    int mode = (mode_arg < 0) ? (int)blockIdx.z : mode_arg;
    int m0 = blockIdx.y << 7, n0 = blockIdx.x << 6;
    if (mode == 3 && m0 >= 2048) return;   // P has only 2048 rows (uniform exit, pre-sync)

    bool two_term = (mode == 3);
    const __half* Ah = (mode <= 2) ? (const __half*)g_xh_
                     : (mode == 3) ? (const __half*)g_peh_ : (const __half*)g_aoh_;
    const __half* Al = (const __half*)g_pel_;   // only used when mode==3
    int widx = (mode <= 2) ? mode : ((mode == 3) ? 3 : 4);
    const uint4* Wb = g_wh_ + (size_t)widx * 32768;

    // ---- stage ALL 8 B chunks (one commit group each) ----
#pragma unroll
    for (int ch = 0; ch < 8; ch++) {
#pragma unroll
        for (int i = 0; i < 2; i++) {
            int idx = tid + i * 256;          // 512: 64 rows x 8 uint4
            int r = idx >> 3, c = idx & 7;
            cpa16(sb + ch * BCH + r * KSTR2 + c * 16,
                  Wb + (size_t)(n0 + r) * 64 + ch * 8 + c);
        }
        CPA_COMMIT();
    }

    int mrow = m0 + 16 * w;

    // ---- A fragment prefetch: chunk 0 ----
    uint32_t Af[2][4][4];
    load_a_chunk(Af[0], Ah, mrow, 0, l);

    float acc[4][2][4];
#pragma unroll
    for (int a = 0; a < 4; a++)
#pragma unroll
        for (int bq2 = 0; bq2 < 2; bq2++)
#pragma unroll
            for (int c = 0; c < 4; c++) acc[a][bq2][c] = 0.f;

    uint32_t kB_rel = (l & 7) * KSTR2 + (l >> 3) * 16;

#pragma unroll
    for (int ch = 0; ch < 8; ch++) {
        if (ch < 7) load_a_chunk(Af[(ch + 1) & 1], Ah, mrow, (ch + 1) * 64, l);
        cpa_wait_dyn(7 - ch);   // B chunks <= ch are complete (groups retire in order)
        __syncthreads();

        uint32_t (*Ac)[4] = Af[ch & 1];
        uint32_t Afl_[4][4];
        if (two_term) load_a_chunk(Afl_, Al, mrow, ch * 64, l);

        uint32_t chb = sb + ch * BCH;
#pragma unroll
        for (int nb = 0; nb < 4; nb++) {
            uint32_t r0 = chb + (16 * nb) * KSTR2 + kB_rel;
            uint32_t r1 = r0 + 8 * KSTR2;
#pragma unroll
            for (int j = 0; j < 2; j++) {
                uint32_t B0[4], B1[4];
                ldsm4(B0, r0 + j * 64);
                ldsm4(B1, r1 + j * 64);
                mma16(acc[nb][0], Ac[2*j],   B0[0], B0[1]);
                mma16(acc[nb][1], Ac[2*j],   B1[0], B1[1]);
                mma16(acc[nb][0], Ac[2*j+1], B0[2], B0[3]);
                mma16(acc[nb][1], Ac[2*j+1], B1[2], B1[3]);
                if (two_term) {
                    mma16(acc[nb][0], Afl_[2*j],   B0[0], B0[1]);
                    mma16(acc[nb][1], Afl_[2*j],   B1[0], B1[1]);
                    mma16(acc[nb][0], Afl_[2*j+1], B0[2], B0[3]);
                    mma16(acc[nb][1], Afl_[2*j+1], B1[2], B1[3]);
                }
            }
        }
        // no trailing sync needed: B chunks are never overwritten
    }

    // ---- epilogue: scatter per mode ----
    int row0 = 16 * w + (l >> 2);
    int m = m0 + row0;          // rows m and m+8
    int colb = (l & 3) << 1;

#pragma unroll
    for (int nb = 0; nb < 4; nb++) {
#pragma unroll
        for (int half = 0; half < 2; half++) {
            int n = n0 + nb * 16 + half * 8 + colb;   // n, n+1
            float c0 = acc[nb][half][0], c1 = acc[nb][half][1];
            float c2 = acc[nb][half][2], c3 = acc[nb][half][3];
            int h = n >> 6, dd = n & 63;

            if (mode == 0) {
                float b0 = bq[n], b1 = bq[n + 1];
                float u0 = pbu[n], u1 = pbu[n + 1];
                float v0 = pbv[n], v1 = pbv[n + 1];
                int bb = m >> 11, t = m & (TT - 1);
                size_t base = ((size_t)(bb * HH + h) * TT + t) * 128 + dd;
                *(uint32_t*)(G_QH + base)      = pack2h((c0+b0+u0)*0.125f, (c1+b1+u1)*0.125f);
                *(uint32_t*)(G_QH + base + 64) = pack2h((c0+b0+v0)*0.125f, (c1+b1+v1)*0.125f);
                size_t base2 = base + (size_t)8 * 128;
                *(uint32_t*)(G_QH + base2)      = pack2h((c2+b0+u0)*0.125f, (c3+b1+u1)*0.125f);
                *(uint32_t*)(G_QH + base2 + 64) = pack2h((c2+b0+v0)*0.125f, (c3+b1+v1)*0.125f);
            } else if (mode == 1) {
                float b0 = bk[n], b1 = bk[n + 1];
                int bb = m >> 11, t = m & (TT - 1);
                size_t base = ((size_t)(bb * HH + h) * TT + t) * 128 + dd;
                *(uint32_t*)(G_KH + base) = pack2h(c0 + b0, c1 + b1);
                *(uint32_t*)(G_KH + base + (size_t)8 * 128) = pack2h(c2 + b0, c3 + b1);
            } else if (mode == 2) {
                float b0 = bv[n], b1 = bv[n + 1];
                int bb = m >> 11, t = m & (TT - 1);
                size_t base = ((size_t)(bb * HH + h) * TT + t) * 64 + dd;
                *(uint32_t*)(G_VH + base) = pack2h(c0 + b0, c1 + b1);
                *(uint32_t*)(G_VH + base + (size_t)8 * 64) = pack2h(c2 + b0, c3 + b1);
            } else if (mode == 3) {
                int t = m;   // 0..2047
                uint32_t p0 = pack2h(c0, c1);
                uint32_t p1 = pack2h(c2, c3);
#pragma unroll
                for (int bb = 0; bb < BB; bb++) {
                    size_t base = ((size_t)(bb * HH + h) * TT + t) * 128 + 64 + dd;
                    *(uint32_t*)(G_KH + base) = p0;
                    *(uint32_t*)(G_KH + base + (size_t)8 * 128) = p1;
                }
            } else {
                float b0 = bout[n], b1 = bout[n + 1];
                *(float2*)(out + (size_t)m * FF + n) = make_float2(c0 + b0, c1 + b1);
                *(float2*)(out + (size_t)(m + 8) * FF + n) = make_float2(c2 + b0, c3 + b1);
            }
        }
    }
}

// ---------------------------------------------------------------------------
// Single-fp16 mma.sync flash attention, ONLINE softmax, 2 CTAs/SM.
// 128-key tiles, double-buffered cp.async. Key-split z in [0,4). (R9-proven)
// ---------------------------------------------------------------------------
#define KSTR 272     // K/Q smem row stride bytes (128 f16 + 16B pad)
#define VSTR 144     // V smem row stride bytes (64 f16 + 16B pad)
#define SM_K 0
#define SM_V 34816
#define STAGE 53248
#define FLASH_SMEM (2*STAGE)   // 106496 -> 2 CTAs/SM

__device__ __forceinline__ void copy_tile_async(uint32_t stb, int bh, int s0, int tid) {
    const uint4* kh = g_kh_ + ((size_t)bh * TT + s0) * 16;
#pragma unroll
    for (int i = 0; i < 8; i++) {
        int idx = tid + i * 256;
        int r = idx >> 4, c = idx & 15;
        cpa16(stb + SM_K + r * KSTR + c * 16, kh + r * 16 + c);
    }
    const uint4* vh = g_vh_ + ((size_t)bh * TT + s0) * 8;
#pragma unroll
    for (int i = 0; i < 4; i++) {
        int idx = tid + i * 256;
        int r = idx >> 3, c = idx & 7;
        cpa16(stb + SM_V + r * VSTR + c * 16, vh + r * 8 + c);
    }
}

__global__ __launch_bounds__(256, 2) void flash_kernel()
{
    extern __shared__ char sm[];
    uint32_t sb = cvta_s(sm);

    int tid = threadIdx.x;
    int w = tid >> 5, l = tid & 31;
    int bh = blockIdx.y;
    int b = bh >> 3, h = bh & 7;
    int t0 = blockIdx.x << 7;
    int z  = blockIdx.z;
    int kbase = z << 9;

    {
        uint32_t qb = sb + STAGE;
        const uint4* qh = g_qh_ + ((size_t)bh * TT + t0) * 16;
#pragma unroll
        for (int i = 0; i < 8; i++) {
            int idx = tid + i * 256;
            int r = idx >> 4, c = idx & 15;
            cpa16(qb + r * KSTR + c * 16, qh + r * 16 + c);
        }
        CPA_COMMIT();
        copy_tile_async(sb, bh, kbase, tid);
        CPA_COMMIT();
    }
    CPA_WAIT1();
    __syncthreads();

    uint32_t Qf[8][4];
    {
        uint32_t rowa = sb + STAGE + (16 * w + (l & 15)) * KSTR + (l >> 4) * 16;
#pragma unroll
        for (int ks = 0; ks < 8; ks++) ldsm4(Qf[ks], rowa + ks * 32);
    }

    float O[8][4];
#pragma unroll
    for (int i = 0; i < 8; i++)
#pragma unroll
        for (int j = 0; j < 4; j++) O[i][j] = 0.f;
    float l_0 = 0.f, l_1 = 0.f;
    float m_0 = -1e30f, m_1 = -1e30f;

    uint32_t kB_rel = (l & 7) * KSTR + (l >> 3) * 16;
    uint32_t vB_rel = ((l & 7) + ((l >> 3) & 1) * 8) * VSTR + (l >> 4) * 16;

    for (int it = 0; it < 4; ++it) {
        __syncthreads();
        if (it < 3) {
            copy_tile_async(sb + ((it + 1) & 1) * STAGE, bh, kbase + ((it + 1) << 7), tid);
            CPA_COMMIT();
            CPA_WAIT1();
        } else {
            CPA_WAIT0();
        }
        __syncthreads();

        uint32_t stb = sb + (it & 1) * STAGE;
        uint32_t kB_lane = stb + kB_rel;
        uint32_t vB_lane = stb + vB_rel;

#pragma unroll
        for (int kb = 0; kb < 8; kb++) {
            float S0A[4] = {0.f,0.f,0.f,0.f}, S0B[4] = {0.f,0.f,0.f,0.f};
            float S1A[4] = {0.f,0.f,0.f,0.f}, S1B[4] = {0.f,0.f,0.f,0.f};
            uint32_t r0a = kB_lane + SM_K + (16 * kb) * KSTR;
            uint32_t r1a = r0a + 8 * KSTR;
#pragma unroll
            for (int j = 0; j < 4; j++) {
                uint32_t B0[4], B1[4];
                ldsm4(B0, r0a + j * 64);
                ldsm4(B1, r1a + j * 64);
                mma16(S0A, Qf[2*j],   B0[0], B0[1]);
                mma16(S1A, Qf[2*j],   B1[0], B1[1]);
                mma16(S0B, Qf[2*j+1], B0[2], B0[3]);
                mma16(S1B, Qf[2*j+1], B1[2], B1[3]);
            }

            uint32_t va = vB_lane + SM_V + (16 * kb) * VSTR;
            uint32_t V0[4], V1[4], V2[4], V3[4];
            ldsm4t(V0, va);
            ldsm4t(V1, va + 32);
            ldsm4t(V2, va + 64);
            ldsm4t(V3, va + 96);

            float s00 = S0A[0]+S0B[0], s01 = S0A[1]+S0B[1];
            float s02 = S0A[2]+S0B[2], s03 = S0A[3]+S0B[3];
            float s10 = S1A[0]+S1B[0], s11 = S1A[1]+S1B[1];
            float s12 = S1A[2]+S1B[2], s13 = S1A[3]+S1B[3];

            float mx0f = fmaxf(fmaxf(s00, s01), fmaxf(s10, s11));
            float mx1f = fmaxf(fmaxf(s02, s03), fmaxf(s12, s13));
            uint32_t pk = pack2h(mx0f, mx1f);
            {
                uint32_t o1 = __shfl_xor_sync(0xffffffffu, pk, 1);
                __half2 a = *reinterpret_cast<__half2*>(&pk);
                __half2 c = __hmax2(a, *reinterpret_cast<__half2*>(&o1));
                pk = *reinterpret_cast<uint32_t*>(&c);
                uint32_t o2 = __shfl_xor_sync(0xffffffffu, pk, 2);
                __half2 d = __hmax2(*reinterpret_cast<__half2*>(&pk),
                                    *reinterpret_cast<__half2*>(&o2));
                pk = *reinterpret_cast<uint32_t*>(&d);
            }
            float2 mxf = __half22float2(*reinterpret_cast<__half2*>(&pk));
            float mn0 = fmaxf(m_0, mxf.x), mn1 = fmaxf(m_1, mxf.y);
            bool nochg = __all_sync(0xffffffffu, (mn0 == m_0) && (mn1 == m_1));

            float p00 = ex2f((s00 - mn0) * LOG2E_F);
            float p01 = ex2f((s01 - mn0) * LOG2E_F);
            float p10 = ex2f((s10 - mn0) * LOG2E_F);
            float p11 = ex2f((s11 - mn0) * LOG2E_F);
            float p02 = ex2f((s02 - mn1) * LOG2E_F);
            float p03 = ex2f((s03 - mn1) * LOG2E_F);
            float p12 = ex2f((s12 - mn1) * LOG2E_F);
            float p13 = ex2f((s13 - mn1) * LOG2E_F);
            float sum0 = (p00 + p01) + (p10 + p11);
            float sum1 = (p02 + p03) + (p12 + p13);

            if (nochg) {
                l_0 += sum0;
                l_1 += sum1;
            } else {
                float c0 = ex2f((m_0 - mn0) * LOG2E_F);
                float c1 = ex2f((m_1 - mn1) * LOG2E_F);
                l_0 = l_0 * c0 + sum0;
                l_1 = l_1 * c1 + sum1;
                m_0 = mn0; m_1 = mn1;
#pragma unroll
                for (int nd = 0; nd < 8; nd++) {
                    O[nd][0] *= c0; O[nd][1] *= c0;
                    O[nd][2] *= c1; O[nd][3] *= c1;
                }
            }

            uint32_t P[4];
            P[0] = pack2h(p00, p01);
            P[1] = pack2h(p02, p03);
            P[2] = pack2h(p10, p11);
            P[3] = pack2h(p12, p13);

            mma16(O[0], P, V0[0], V0[1]);
            mma16(O[1], P, V0[2], V0[3]);
            mma16(O[2], P, V1[0], V1[1]);
            mma16(O[3], P, V1[2], V1[3]);
            mma16(O[4], P, V2[0], V2[1]);
            mma16(O[5], P, V2[2], V2[3]);
            mma16(O[6], P, V3[0], V3[1]);
            mma16(O[7], P, V3[2], V3[3]);
        }
    }

    l_0 += __shfl_xor_sync(0xffffffffu, l_0, 1);
    l_0 += __shfl_xor_sync(0xffffffffu, l_0, 2);
    l_1 += __shfl_xor_sync(0xffffffffu, l_1, 1);
    l_1 += __shfl_xor_sync(0xffffffffu, l_1, 2);

    float* po = g_po + (size_t)z * MM * FF;
    float* ls = g_ls + z * 32 * TT;
    float* lm = g_lm + z * 32 * TT;

    int row0 = t0 + 16 * w + (l >> 2);
    if ((l & 3) == 0) {
        ls[bh * TT + row0] = l_0;      lm[bh * TT + row0] = m_0;
        ls[bh * TT + row0 + 8] = l_1;  lm[bh * TT + row0 + 8] = m_1;
    }
    float* d0 = po + ((size_t)(b * TT + row0)) * FF + (h << 6) + ((l & 3) << 1);
    float* d1 = d0 + (size_t)8 * FF;
#pragma unroll
    for (int nd = 0; nd < 8; nd++) {
        *(float2*)(d0 + nd * 8) = make_float2(O[nd][0], O[nd][1]);
        *(float2*)(d1 + nd * 8) = make_float2(O[nd][2], O[nd][3]);
    }
}

// ---------------------------------------------------------------------------
// combine NZ partials with (m,l) merge -> single fp16 ao (feeds OUT gemm)
// ---------------------------------------------------------------------------
__global__ __launch_bounds__(256) void combine_kernel()
{
    int idx = blockIdx.x * 256 + threadIdx.x;   // float4 units over MM*FF
    int m = idx >> 7;
    int c = (idx & 127) << 2;
    int h = c >> 6;
    int b = m >> 11, t = m & (TT - 1);
    int r = (b * HH + h) * TT + t;

    float mz[NZ];
    float M = -1e30f;
#pragma unroll
    for (int zz = 0; zz < NZ; zz++) { mz[zz] = g_lm[zz * 32 * TT + r]; M = fmaxf(M, mz[zz]); }
    float L = 0.f;
    float wz[NZ];
#pragma unroll
    for (int zz = 0; zz < NZ; zz++) {
        wz[zz] = ex2f((mz[zz] - M) * LOG2E_F);
        L += g_ls[zz * 32 * TT + r] * wz[zz];
    }
    float inv = 1.f / L;

    float4 acc = make_float4(0.f, 0.f, 0.f, 0.f);
#pragma unroll
    for (int zz = 0; zz < NZ; zz++) {
        float4 o = *(const float4*)(g_po + (size_t)zz * MM * FF + (size_t)idx * 4);
        acc.x += o.x * wz[zz]; acc.y += o.y * wz[zz];
        acc.z += o.z * wz[zz]; acc.w += o.w * wz[zz];
    }
    ((uint2*)g_aoh_)[idx] = make_uint2(pack2h(acc.x * inv, acc.y * inv),
                                       pack2h(acc.z * inv, acc.w * inv));
}

// ---------------------------------------------------------------------------
extern "C" void kernel_launch(void* const* d_in, const int* in_sizes, int n_in,
                              void* d_out, int out_size)
{
    const float* x    = (const float*)d_in[0];
    const float* pe   = (const float*)d_in[1];
    const float* Wq   = (const float*)d_in[2];
    const float* bq   = (const float*)d_in[3];
    const float* Wk   = (const float*)d_in[4];
    const float* bk   = (const float*)d_in[5];
    const float* Wv   = (const float*)d_in[6];
    const float* bv   = (const float*)d_in[7];
    const float* Wpos = (const float*)d_in[8];
    const float* Wout = (const float*)d_in[9];
    const float* bout = (const float*)d_in[10];
    const float* pbu  = (const float*)d_in[11];
    const float* pbv  = (const float*)d_in[12];
    float* out = (float*)d_out;

    cudaFuncSetAttribute(flash_kernel, cudaFuncAttributeMaxDynamicSharedMemorySize, FLASH_SMEM);
    cudaFuncSetAttribute(proj_kernel, cudaFuncAttributeMaxDynamicSharedMemorySize, GEMM_SMEM);

    dim3 blk(256);
    // #0: fp32 -> fp16 conversions (x, pe hi/lo, 5 weights)
    conv_kernel<<<dim3(512, 7), blk>>>(x, pe, Wq, Wk, Wv, Wpos, Wout);
    // #1: fused QKV + P projections (tensor cores; z=3 = P, masked to y<16)
    proj_kernel<<<dim3(8, 64, 4), blk, GEMM_SMEM>>>(-1, nullptr, bq, bk, bv, bout, pbu, pbv);
    // #2: flash attention
    flash_kernel<<<dim3(TT / 128, BB * HH, NZ), blk, FLASH_SMEM>>>();
    // #3: combine split-K partials -> fp16 ao
    combine_kernel<<<dim3((MM * FF) / 1024), blk>>>();
    // #4: output projection (tensor cores, single-term A) -> d_out
    proj_kernel<<<dim3(8, 64, 1), blk, GEMM_SMEM>>>(4, out, bq, bk, bv, bout, pbu, pbv);
}

// round 16
// speedup vs baseline: 1.0960x; 1.0960x over previous
#include <cuda_runtime.h>
#include <cuda_bf16.h>
#include <cuda_fp16.h>
#include <cstdint>

#define BB 4
#define TT 2048
#define HH 8
#define FF 512
#define MM (BB*TT)   // 8192
#define NZ 4         // key-split factor

// ---------------------------------------------------------------------------
// Global scratch (device globals; uint4 for 16B alignment)
// ---------------------------------------------------------------------------
__device__ uint4 g_qh_[1048576];   // q_cat fp16: [bh=32][t=2048][128] (scaled 0.125, biases fused)
__device__ uint4 g_kh_[1048576];   // k_cat fp16: [bh][t][0:64]=k, [64:128]=p
__device__ uint4 g_vh_[524288];    // V fp16: [bh][t][64]
__device__ uint4 g_xh_[524288];    // x fp16 [8192][512] (single term)
__device__ uint4 g_peh_[131072];   // pos_emb hi fp16 [2048][512]
__device__ uint4 g_pel_[131072];   // pos_emb lo fp16
__device__ uint4 g_wh_[163840];    // 5 weights fp16 [5][512][512] (Wq,Wk,Wv,Wpos,Wout)
__device__ uint4 g_aoh_[524288];   // attention-out fp16 [8192][512] (single term)
__device__ float g_po[(size_t)NZ*MM*FF];  // partial O per z, unnormalized
__device__ float g_ls[NZ*32*TT];          // partial row sums
__device__ float g_lm[NZ*32*TT];          // partial row maxes

#define G_QH ((__half*)g_qh_)
#define G_KH ((__half*)g_kh_)
#define G_VH ((__half*)g_vh_)

// ---------------------------------------------------------------------------
__device__ __forceinline__ uint32_t cvta_s(const void* p) {
    return (uint32_t)__cvta_generic_to_shared(p);
}
__device__ __forceinline__ float ex2f(float x) {
    float r; asm("ex2.approx.ftz.f32 %0, %1;" : "=f"(r) : "f"(x)); return r;
}
// pack two f32 -> f16x2 word: first arg -> low half, second -> high half
__device__ __forceinline__ uint32_t pack2h(float lo, float hi) {
    uint32_t r; asm("cvt.rn.f16x2.f32 %0, %1, %2;" : "=r"(r) : "f"(hi), "f"(lo)); return r;
}

__device__ __forceinline__ void ldsm4(uint32_t r[4], uint32_t a) {
    asm volatile("ldmatrix.sync.aligned.m8n8.x4.shared.b16 {%0,%1,%2,%3}, [%4];"
                 : "=r"(r[0]), "=r"(r[1]), "=r"(r[2]), "=r"(r[3]) : "r"(a));
}
__device__ __forceinline__ void ldsm4t(uint32_t r[4], uint32_t a) {
    asm volatile("ldmatrix.sync.aligned.m8n8.x4.trans.shared.b16 {%0,%1,%2,%3}, [%4];"
                 : "=r"(r[0]), "=r"(r[1]), "=r"(r[2]), "=r"(r[3]) : "r"(a));
}
// fp16 mma, f32 accumulate. Non-volatile: pure register op.
__device__ __forceinline__ void mma16(float c[4], const uint32_t a[4], uint32_t b0, uint32_t b1) {
    asm("mma.sync.aligned.m16n8k16.row.col.f32.f16.f16.f32 "
        "{%0,%1,%2,%3}, {%4,%5,%6,%7}, {%8,%9}, {%0,%1,%2,%3};"
        : "+f"(c[0]), "+f"(c[1]), "+f"(c[2]), "+f"(c[3])
        : "r"(a[0]), "r"(a[1]), "r"(a[2]), "r"(a[3]), "r"(b0), "r"(b1));
}

__device__ __forceinline__ void cpa16(uint32_t d, const void* s) {
    asm volatile("cp.async.cg.shared.global [%0], [%1], 16;" :: "r"(d), "l"(s) : "memory");
}
#define CPA_COMMIT() asm volatile("cp.async.commit_group;" ::: "memory")
#define CPA_WAIT1()  asm volatile("cp.async.wait_group 1;" ::: "memory")
#define CPA_WAIT0()  asm volatile("cp.async.wait_group 0;" ::: "memory")

#define LOG2E_F 1.4426950408889634f

// ---------------------------------------------------------------------------
// conv_kernel: fp32 -> fp16 conversions.
// z=0: x -> g_xh (single term). z=1: pos_emb -> g_peh/g_pel (hi/lo).
// z=2..6: Wq,Wk,Wv,Wpos,Wout -> g_wh (single fp16).
// ---------------------------------------------------------------------------
__global__ __launch_bounds__(256) void conv_kernel(
    const float* __restrict__ x, const float* __restrict__ pe,
    const float* __restrict__ Wq, const float* __restrict__ Wk,
    const float* __restrict__ Wv, const float* __restrict__ Wpos,
    const float* __restrict__ Wout)
{
    int z = blockIdx.y;
    int stride = gridDim.x * 256;
    if (z == 0) {
        const float4* src = (const float4*)x;
        uint2* dh = (uint2*)g_xh_;
        for (int i = blockIdx.x * 256 + threadIdx.x; i < 1048576; i += stride) {
            float4 v = src[i];
            dh[i] = make_uint2(pack2h(v.x, v.y), pack2h(v.z, v.w));
        }
    } else if (z == 1) {
        const float4* src = (const float4*)pe;
        uint2* dh = (uint2*)g_peh_;
        uint2* dl = (uint2*)g_pel_;
        for (int i = blockIdx.x * 256 + threadIdx.x; i < 262144; i += stride) {
            float4 v = src[i];
            uint32_t h0 = pack2h(v.x, v.y);
            uint32_t h1 = pack2h(v.z, v.w);
            float2 f0 = __half22float2(*reinterpret_cast<__half2*>(&h0));
            float2 f1 = __half22float2(*reinterpret_cast<__half2*>(&h1));
            dh[i] = make_uint2(h0, h1);
            dl[i] = make_uint2(pack2h(v.x - f0.x, v.y - f0.y), pack2h(v.z - f1.x, v.w - f1.y));
        }
    } else {
        int widx = z - 2;
        const float* Wsel = (widx == 0) ? Wq : (widx == 1) ? Wk : (widx == 2) ? Wv
                          : (widx == 3) ? Wpos : Wout;
        const float4* src = (const float4*)Wsel;
        uint2* dh = (uint2*)g_wh_ + (size_t)widx * 65536;
        for (int i = blockIdx.x * 256 + threadIdx.x; i < 65536; i += stride) {
            float4 v = src[i];
            dh[i] = make_uint2(pack2h(v.x, v.y), pack2h(v.z, v.w));
        }
    }
}

// ---------------------------------------------------------------------------
// fp16 tensor-core projection GEMM (R12 structure, N-tile widened to 128):
// CTA: 128 rows x 128 cols, 8 warps. K=512 in 8 chunks of 64, double-buffered
// cp.async stages (A [+Al for P] and B per stage).
// mode (blockIdx.z if arg<0): 0=Q, 1=K, 2=V, 3=P, 4=OUT — scatter epilogues.
// Only mode 3 (P) uses the 2-term A split.
// ---------------------------------------------------------------------------
#define KSTR2 144              // 64 f16 + 16B pad
#define SM_AH 0
#define SM_AL 18432
#define SM_B  36864            // B chunk: 128 rows x 144B = 18432
#define GSTAGE 55296
#define GEMM_SMEM (2*GSTAGE)   // 110592 -> 2 CTAs/SM

__device__ __forceinline__ void copy_gtile(
    uint32_t stb, const uint4* Ah, const uint4* Al, const uint4* Wb,
    int m0, int n0, int k08, int tid, bool two_term)
{
#pragma unroll
    for (int i = 0; i < 4; i++) {
        int idx = tid + i * 256;          // 1024: 128 rows x 8 uint4
        int r = idx >> 3, c = idx & 7;
        size_t so = (size_t)(m0 + r) * 64 + k08 + c;
        cpa16(stb + SM_AH + r * KSTR2 + c * 16, Ah + so);
        if (two_term) cpa16(stb + SM_AL + r * KSTR2 + c * 16, Al + so);
    }
#pragma unroll
    for (int i = 0; i < 4; i++) {
        int idx = tid + i * 256;          // 1024: 128 B-rows x 8 uint4
        int r = idx >> 3, c = idx & 7;
        cpa16(stb + SM_B + r * KSTR2 + c * 16, Wb + (size_t)(n0 + r) * 64 + k08 + c);
    }
}

__global__ __launch_bounds__(256, 2) void proj_kernel(
    int mode_arg, float* __restrict__ out,
    const float* __restrict__ bq, const float* __restrict__ bk,
    const float* __restrict__ bv, const float* __restrict__ bout,
    const float* __restrict__ pbu, const float* __restrict__ pbv)
{
    extern __shared__ char sm[];
    uint32_t sb = cvta_s(sm);

    int tid = threadIdx.x;
    int w = tid >> 5, l = tid & 31;
    int mode = (mode_arg < 0) ? (int)blockIdx.z : mode_arg;
    int m0 = blockIdx.y << 7, n0 = blockIdx.x << 7;
    if (mode == 3 && m0 >= 2048) return;   // P has only 2048 rows (uniform exit, pre-sync)

    bool two_term = (mode == 3);
    const uint4* Ah = (mode <= 2) ? g_xh_ : (mode == 3) ? g_peh_ : g_aoh_;
    const uint4* Al = g_pel_;              // only used when mode==3
    int widx = (mode <= 2) ? mode : ((mode == 3) ? 3 : 4);
    const uint4* Wb = g_wh_ + (size_t)widx * 32768;

    // prologue: chunks 0,1
    copy_gtile(sb, Ah, Al, Wb, m0, n0, 0, tid, two_term);  CPA_COMMIT();
    copy_gtile(sb + GSTAGE, Ah, Al, Wb, m0, n0, 8, tid, two_term);  CPA_COMMIT();

    float acc[8][2][4];
#pragma unroll
    for (int a = 0; a < 8; a++)
#pragma unroll
        for (int bq2 = 0; bq2 < 2; bq2++)
#pragma unroll
            for (int c = 0; c < 4; c++) acc[a][bq2][c] = 0.f;

    uint32_t rowa_rel = (16 * w + (l & 15)) * KSTR2 + (l >> 4) * 16;
    uint32_t kB_rel   = (l & 7) * KSTR2 + (l >> 3) * 16;

    for (int ch = 0; ch < 8; ch++) {
        if (ch < 6) { CPA_WAIT1(); } else { CPA_WAIT0(); }
        __syncthreads();

        uint32_t stb = sb + (ch & 1) * GSTAGE;

        uint32_t Afh[4][4], Afl[4][4];
#pragma unroll
        for (int ks = 0; ks < 4; ks++) {
            ldsm4(Afh[ks], stb + SM_AH + rowa_rel + ks * 32);
            if (two_term) ldsm4(Afl[ks], stb + SM_AL + rowa_rel + ks * 32);
        }
#pragma unroll
        for (int nb = 0; nb < 8; nb++) {
            uint32_t r0 = stb + SM_B + (16 * nb) * KSTR2 + kB_rel;
            uint32_t r1 = r0 + 8 * KSTR2;
#pragma unroll
            for (int j = 0; j < 2; j++) {
                uint32_t B0[4], B1[4];
                ldsm4(B0, r0 + j * 64);
                ldsm4(B1, r1 + j * 64);
                mma16(acc[nb][0], Afh[2*j],   B0[0], B0[1]);
                mma16(acc[nb][1], Afh[2*j],   B1[0], B1[1]);
                mma16(acc[nb][0], Afh[2*j+1], B0[2], B0[3]);
                mma16(acc[nb][1], Afh[2*j+1], B1[2], B1[3]);
                if (two_term) {
                    mma16(acc[nb][0], Afl[2*j],   B0[0], B0[1]);
                    mma16(acc[nb][1], Afl[2*j],   B1[0], B1[1]);
                    mma16(acc[nb][0], Afl[2*j+1], B0[2], B0[3]);
                    mma16(acc[nb][1], Afl[2*j+1], B1[2], B1[3]);
                }
            }
        }
        __syncthreads();
        if (ch + 2 < 8) {
            copy_gtile(sb + (ch & 1) * GSTAGE, Ah, Al, Wb, m0, n0, (ch + 2) * 8, tid, two_term);
            CPA_COMMIT();
        }
    }

    // ---- epilogue: scatter per mode ----
    int row0 = 16 * w + (l >> 2);
    int m = m0 + row0;          // rows m and m+8
    int colb = (l & 3) << 1;

#pragma unroll
    for (int nb = 0; nb < 8; nb++) {
#pragma unroll
        for (int half = 0; half < 2; half++) {
            int n = n0 + nb * 16 + half * 8 + colb;   // n, n+1
            float c0 = acc[nb][half][0], c1 = acc[nb][half][1];
            float c2 = acc[nb][half][2], c3 = acc[nb][half][3];
            int h = n >> 6, dd = n & 63;

            if (mode == 0) {
                float b0 = bq[n], b1 = bq[n + 1];
                float u0 = pbu[n], u1 = pbu[n + 1];
                float v0 = pbv[n], v1 = pbv[n + 1];
                int bb = m >> 11, t = m & (TT - 1);
                size_t base = ((size_t)(bb * HH + h) * TT + t) * 128 + dd;
                *(uint32_t*)(G_QH + base)      = pack2h((c0+b0+u0)*0.125f, (c1+b1+u1)*0.125f);
                *(uint32_t*)(G_QH + base + 64) = pack2h((c0+b0+v0)*0.125f, (c1+b1+v1)*0.125f);
                size_t base2 = base + (size_t)8 * 128;
                *(uint32_t*)(G_QH + base2)      = pack2h((c2+b0+u0)*0.125f, (c3+b1+u1)*0.125f);
                *(uint32_t*)(G_QH + base2 + 64) = pack2h((c2+b0+v0)*0.125f, (c3+b1+v1)*0.125f);
            } else if (mode == 1) {
                float b0 = bk[n], b1 = bk[n + 1];
                int bb = m >> 11, t = m & (TT - 1);
                size_t base = ((size_t)(bb * HH + h) * TT + t) * 128 + dd;
                *(uint32_t*)(G_KH + base) = pack2h(c0 + b0, c1 + b1);
                *(uint32_t*)(G_KH + base + (size_t)8 * 128) = pack2h(c2 + b0, c3 + b1);
            } else if (mode == 2) {
                float b0 = bv[n], b1 = bv[n + 1];
                int bb = m >> 11, t = m & (TT - 1);
                size_t base = ((size_t)(bb * HH + h) * TT + t) * 64 + dd;
                *(uint32_t*)(G_VH + base) = pack2h(c0 + b0, c1 + b1);
                *(uint32_t*)(G_VH + base + (size_t)8 * 64) = pack2h(c2 + b0, c3 + b1);
            } else if (mode == 3) {
                int t = m;   // 0..2047
                uint32_t p0 = pack2h(c0, c1);
                uint32_t p1 = pack2h(c2, c3);
#pragma unroll
                for (int bb = 0; bb < BB; bb++) {
                    size_t base = ((size_t)(bb * HH + h) * TT + t) * 128 + 64 + dd;
                    *(uint32_t*)(G_KH + base) = p0;
                    *(uint32_t*)(G_KH + base + (size_t)8 * 128) = p1;
                }
            } else {
                float b0 = bout[n], b1 = bout[n + 1];
                *(float2*)(out + (size_t)m * FF + n) = make_float2(c0 + b0, c1 + b1);
                *(float2*)(out + (size_t)(m + 8) * FF + n) = make_float2(c2 + b0, c3 + b1);
            }
        }
    }
}

// ---------------------------------------------------------------------------
// Single-fp16 mma.sync flash attention, ONLINE softmax, 2 CTAs/SM.
// 128-key tiles, double-buffered cp.async. Key-split z in [0,4). (R9-proven)
// ---------------------------------------------------------------------------
#define KSTR 272     // K/Q smem row stride bytes (128 f16 + 16B pad)
#define VSTR 144     // V smem row stride bytes (64 f16 + 16B pad)
#define SM_K 0
#define SM_V 34816
#define STAGE 53248
#define FLASH_SMEM (2*STAGE)   // 106496 -> 2 CTAs/SM

__device__ __forceinline__ void copy_tile_async(uint32_t stb, int bh, int s0, int tid) {
    const uint4* kh = g_kh_ + ((size_t)bh * TT + s0) * 16;
#pragma unroll
    for (int i = 0; i < 8; i++) {
        int idx = tid + i * 256;
        int r = idx >> 4, c = idx & 15;
        cpa16(stb + SM_K + r * KSTR + c * 16, kh + r * 16 + c);
    }
    const uint4* vh = g_vh_ + ((size_t)bh * TT + s0) * 8;
#pragma unroll
    for (int i = 0; i < 4; i++) {
        int idx = tid + i * 256;
        int r = idx >> 3, c = idx & 7;
        cpa16(stb + SM_V + r * VSTR + c * 16, vh + r * 8 + c);
    }
}

__global__ __launch_bounds__(256, 2) void flash_kernel()
{
    extern __shared__ char sm[];
    uint32_t sb = cvta_s(sm);

    int tid = threadIdx.x;
    int w = tid >> 5, l = tid & 31;
    int bh = blockIdx.y;
    int b = bh >> 3, h = bh & 7;
    int t0 = blockIdx.x << 7;
    int z  = blockIdx.z;
    int kbase = z << 9;

    {
        uint32_t qb = sb + STAGE;
        const uint4* qh = g_qh_ + ((size_t)bh * TT + t0) * 16;
#pragma unroll
        for (int i = 0; i < 8; i++) {
            int idx = tid + i * 256;
            int r = idx >> 4, c = idx & 15;
            cpa16(qb + r * KSTR + c * 16, qh + r * 16 + c);
        }
        CPA_COMMIT();
        copy_tile_async(sb, bh, kbase, tid);
        CPA_COMMIT();
    }
    CPA_WAIT1();
    __syncthreads();

    uint32_t Qf[8][4];
    {
        uint32_t rowa = sb + STAGE + (16 * w + (l & 15)) * KSTR + (l >> 4) * 16;
#pragma unroll
        for (int ks = 0; ks < 8; ks++) ldsm4(Qf[ks], rowa + ks * 32);
    }

    float O[8][4];
#pragma unroll
    for (int i = 0; i < 8; i++)
#pragma unroll
        for (int j = 0; j < 4; j++) O[i][j] = 0.f;
    float l_0 = 0.f, l_1 = 0.f;
    float m_0 = -1e30f, m_1 = -1e30f;

    uint32_t kB_rel = (l & 7) * KSTR + (l >> 3) * 16;
    uint32_t vB_rel = ((l & 7) + ((l >> 3) & 1) * 8) * VSTR + (l >> 4) * 16;

    for (int it = 0; it < 4; ++it) {
        __syncthreads();
        if (it < 3) {
            copy_tile_async(sb + ((it + 1) & 1) * STAGE, bh, kbase + ((it + 1) << 7), tid);
            CPA_COMMIT();
            CPA_WAIT1();
        } else {
            CPA_WAIT0();
        }
        __syncthreads();

        uint32_t stb = sb + (it & 1) * STAGE;
        uint32_t kB_lane = stb + kB_rel;
        uint32_t vB_lane = stb + vB_rel;

#pragma unroll
        for (int kb = 0; kb < 8; kb++) {
            float S0A[4] = {0.f,0.f,0.f,0.f}, S0B[4] = {0.f,0.f,0.f,0.f};
            float S1A[4] = {0.f,0.f,0.f,0.f}, S1B[4] = {0.f,0.f,0.f,0.f};
            uint32_t r0a = kB_lane + SM_K + (16 * kb) * KSTR;
            uint32_t r1a = r0a + 8 * KSTR;
#pragma unroll
            for (int j = 0; j < 4; j++) {
                uint32_t B0[4], B1[4];
                ldsm4(B0, r0a + j * 64);
                ldsm4(B1, r1a + j * 64);
                mma16(S0A, Qf[2*j],   B0[0], B0[1]);
                mma16(S1A, Qf[2*j],   B1[0], B1[1]);
                mma16(S0B, Qf[2*j+1], B0[2], B0[3]);
                mma16(S1B, Qf[2*j+1], B1[2], B1[3]);
            }

            uint32_t va = vB_lane + SM_V + (16 * kb) * VSTR;
            uint32_t V0[4], V1[4], V2[4], V3[4];
            ldsm4t(V0, va);
            ldsm4t(V1, va + 32);
            ldsm4t(V2, va + 64);
            ldsm4t(V3, va + 96);

            float s00 = S0A[0]+S0B[0], s01 = S0A[1]+S0B[1];
            float s02 = S0A[2]+S0B[2], s03 = S0A[3]+S0B[3];
            float s10 = S1A[0]+S1B[0], s11 = S1A[1]+S1B[1];
            float s12 = S1A[2]+S1B[2], s13 = S1A[3]+S1B[3];

            float mx0f = fmaxf(fmaxf(s00, s01), fmaxf(s10, s11));
            float mx1f = fmaxf(fmaxf(s02, s03), fmaxf(s12, s13));
            uint32_t pk = pack2h(mx0f, mx1f);
            {
                uint32_t o1 = __shfl_xor_sync(0xffffffffu, pk, 1);
                __half2 a = *reinterpret_cast<__half2*>(&pk);
                __half2 c = __hmax2(a, *reinterpret_cast<__half2*>(&o1));
                pk = *reinterpret_cast<uint32_t*>(&c);
                uint32_t o2 = __shfl_xor_sync(0xffffffffu, pk, 2);
                __half2 d = __hmax2(*reinterpret_cast<__half2*>(&pk),
                                    *reinterpret_cast<__half2*>(&o2));
                pk = *reinterpret_cast<uint32_t*>(&d);
            }
            float2 mxf = __half22float2(*reinterpret_cast<__half2*>(&pk));
            float mn0 = fmaxf(m_0, mxf.x), mn1 = fmaxf(m_1, mxf.y);
            bool nochg = __all_sync(0xffffffffu, (mn0 == m_0) && (mn1 == m_1));

            float p00 = ex2f((s00 - mn0) * LOG2E_F);
            float p01 = ex2f((s01 - mn0) * LOG2E_F);
            float p10 = ex2f((s10 - mn0) * LOG2E_F);
            float p11 = ex2f((s11 - mn0) * LOG2E_F);
            float p02 = ex2f((s02 - mn1) * LOG2E_F);
            float p03 = ex2f((s03 - mn1) * LOG2E_F);
            float p12 = ex2f((s12 - mn1) * LOG2E_F);
            float p13 = ex2f((s13 - mn1) * LOG2E_F);
            float sum0 = (p00 + p01) + (p10 + p11);
            float sum1 = (p02 + p03) + (p12 + p13);

            if (nochg) {
                l_0 += sum0;
                l_1 += sum1;
            } else {
                float c0 = ex2f((m_0 - mn0) * LOG2E_F);
                float c1 = ex2f((m_1 - mn1) * LOG2E_F);
                l_0 = l_0 * c0 + sum0;
                l_1 = l_1 * c1 + sum1;
                m_0 = mn0; m_1 = mn1;
#pragma unroll
                for (int nd = 0; nd < 8; nd++) {
                    O[nd][0] *= c0; O[nd][1] *= c0;
                    O[nd][2] *= c1; O[nd][3] *= c1;
                }
            }

            uint32_t P[4];
            P[0] = pack2h(p00, p01);
            P[1] = pack2h(p02, p03);
            P[2] = pack2h(p10, p11);
            P[3] = pack2h(p12, p13);

            mma16(O[0], P, V0[0], V0[1]);
            mma16(O[1], P, V0[2], V0[3]);
            mma16(O[2], P, V1[0], V1[1]);
            mma16(O[3], P, V1[2], V1[3]);
            mma16(O[4], P, V2[0], V2[1]);
            mma16(O[5], P, V2[2], V2[3]);
            mma16(O[6], P, V3[0], V3[1]);
            mma16(O[7], P, V3[2], V3[3]);
        }
    }

    l_0 += __shfl_xor_sync(0xffffffffu, l_0, 1);
    l_0 += __shfl_xor_sync(0xffffffffu, l_0, 2);
    l_1 += __shfl_xor_sync(0xffffffffu, l_1, 1);
    l_1 += __shfl_xor_sync(0xffffffffu, l_1, 2);

    float* po = g_po + (size_t)z * MM * FF;
    float* ls = g_ls + z * 32 * TT;
    float* lm = g_lm + z * 32 * TT;

    int row0 = t0 + 16 * w + (l >> 2);
    if ((l & 3) == 0) {
        ls[bh * TT + row0] = l_0;      lm[bh * TT + row0] = m_0;
        ls[bh * TT + row0 + 8] = l_1;  lm[bh * TT + row0 + 8] = m_1;
    }
    float* d0 = po + ((size_t)(b * TT + row0)) * FF + (h << 6) + ((l & 3) << 1);
    float* d1 = d0 + (size_t)8 * FF;
#pragma unroll
    for (int nd = 0; nd < 8; nd++) {
        *(float2*)(d0 + nd * 8) = make_float2(O[nd][0], O[nd][1]);
        *(float2*)(d1 + nd * 8) = make_float2(O[nd][2], O[nd][3]);
    }
}

// ---------------------------------------------------------------------------
// combine NZ partials with (m,l) merge -> single fp16 ao (feeds OUT gemm)
// ---------------------------------------------------------------------------
__global__ __launch_bounds__(256) void combine_kernel()
{
    int idx = blockIdx.x * 256 + threadIdx.x;   // float4 units over MM*FF
    int m = idx >> 7;
    int c = (idx & 127) << 2;
    int h = c >> 6;
    int b = m >> 11, t = m & (TT - 1);
    int r = (b * HH + h) * TT + t;

    float mz[NZ];
    float M = -1e30f;
#pragma unroll
    for (int zz = 0; zz < NZ; zz++) { mz[zz] = g_lm[zz * 32 * TT + r]; M = fmaxf(M, mz[zz]); }
    float L = 0.f;
    float wz[NZ];
#pragma unroll
    for (int zz = 0; zz < NZ; zz++) {
        wz[zz] = ex2f((mz[zz] - M) * LOG2E_F);
        L += g_ls[zz * 32 * TT + r] * wz[zz];
    }
    float inv = 1.f / L;

    float4 acc = make_float4(0.f, 0.f, 0.f, 0.f);
#pragma unroll
    for (int zz = 0; zz < NZ; zz++) {
        float4 o = *(const float4*)(g_po + (size_t)zz * MM * FF + (size_t)idx * 4);
        acc.x += o.x * wz[zz]; acc.y += o.y * wz[zz];
        acc.z += o.z * wz[zz]; acc.w += o.w * wz[zz];
    }
    ((uint2*)g_aoh_)[idx] = make_uint2(pack2h(acc.x * inv, acc.y * inv),
                                       pack2h(acc.z * inv, acc.w * inv));
}

// ---------------------------------------------------------------------------
extern "C" void kernel_launch(void* const* d_in, const int* in_sizes, int n_in,
                              void* d_out, int out_size)
{
    const float* x    = (const float*)d_in[0];
    const float* pe   = (const float*)d_in[1];
    const float* Wq   = (const float*)d_in[2];
    const float* bq   = (const float*)d_in[3];
    const float* Wk   = (const float*)d_in[4];
    const float* bk   = (const float*)d_in[5];
    const float* Wv   = (const float*)d_in[6];
    const float* bv   = (const float*)d_in[7];
    const float* Wpos = (const float*)d_in[8];
    const float* Wout = (const float*)d_in[9];
    const float* bout = (const float*)d_in[10];
    const float* pbu  = (const float*)d_in[11];
    const float* pbv  = (const float*)d_in[12];
    float* out = (float*)d_out;

    cudaFuncSetAttribute(flash_kernel, cudaFuncAttributeMaxDynamicSharedMemorySize, FLASH_SMEM);
    cudaFuncSetAttribute(proj_kernel, cudaFuncAttributeMaxDynamicSharedMemorySize, GEMM_SMEM);

    dim3 blk(256);
    // #0: fp32 -> fp16 conversions (x, pe hi/lo, 5 weights)
    conv_kernel<<<dim3(512, 7), blk>>>(x, pe, Wq, Wk, Wv, Wpos, Wout);
    // #1: fused QKV + P projections (tensor cores; z=3 = P, masked to y<16)
    proj_kernel<<<dim3(4, 64, 4), blk, GEMM_SMEM>>>(-1, nullptr, bq, bk, bv, bout, pbu, pbv);
    // #2: flash attention
    flash_kernel<<<dim3(TT / 128, BB * HH, NZ), blk, FLASH_SMEM>>>();
    // #3: combine split-K partials -> fp16 ao
    combine_kernel<<<dim3((MM * FF) / 1024), blk>>>();
    // #4: output projection (tensor cores, single-term A) -> d_out
    proj_kernel<<<dim3(4, 64, 1), blk, GEMM_SMEM>>>(4, out, bq, bk, bv, bout, pbu, pbv);
}

// round 17
// speedup vs baseline: 1.1059x; 1.0091x over previous
#include <cuda_runtime.h>
#include <cuda_bf16.h>
#include <cuda_fp16.h>
#include <cstdint>

#define BB 4
#define TT 2048
#define HH 8
#define FF 512
#define MM (BB*TT)   // 8192
#define NZ 4         // key-split factor

// ---------------------------------------------------------------------------
// Global scratch (device globals; uint4/uint2 for alignment)
// ---------------------------------------------------------------------------
__device__ uint4 g_qh_[1048576];   // q_cat fp16: [bh=32][t=2048][128] (scaled 0.125, biases fused)
__device__ uint4 g_kh_[1048576];   // k_cat fp16: [bh][t][0:64]=k, [64:128]=p
__device__ uint4 g_vh_[524288];    // V fp16: [bh][t][64]
__device__ uint4 g_xh_[524288];    // x fp16 [8192][512] (single term)
__device__ uint4 g_peh_[131072];   // pos_emb hi fp16 [2048][512]
__device__ uint4 g_pel_[131072];   // pos_emb lo fp16
__device__ uint4 g_wh_[163840];    // 5 weights fp16 [5][512][512] (Wq,Wk,Wv,Wpos,Wout)
__device__ uint4 g_aoh_[524288];   // attention-out fp16 [8192][512] (single term)
__device__ uint2 g_po16[(size_t)NZ*MM*FF/4];  // partial O per z, fp16, unnormalized
__device__ float g_ls[NZ*32*TT];          // partial row sums
__device__ float g_lm[NZ*32*TT];          // partial row maxes

#define G_QH ((__half*)g_qh_)
#define G_KH ((__half*)g_kh_)
#define G_VH ((__half*)g_vh_)

// ---------------------------------------------------------------------------
__device__ __forceinline__ uint32_t cvta_s(const void* p) {
    return (uint32_t)__cvta_generic_to_shared(p);
}
__device__ __forceinline__ float ex2f(float x) {
    float r; asm("ex2.approx.ftz.f32 %0, %1;" : "=f"(r) : "f"(x)); return r;
}
// pack two f32 -> f16x2 word: first arg -> low half, second -> high half
__device__ __forceinline__ uint32_t pack2h(float lo, float hi) {
    uint32_t r; asm("cvt.rn.f16x2.f32 %0, %1, %2;" : "=r"(r) : "f"(hi), "f"(lo)); return r;
}

__device__ __forceinline__ void ldsm4(uint32_t r[4], uint32_t a) {
    asm volatile("ldmatrix.sync.aligned.m8n8.x4.shared.b16 {%0,%1,%2,%3}, [%4];"
                 : "=r"(r[0]), "=r"(r[1]), "=r"(r[2]), "=r"(r[3]) : "r"(a));
}
__device__ __forceinline__ void ldsm4t(uint32_t r[4], uint32_t a) {
    asm volatile("ldmatrix.sync.aligned.m8n8.x4.trans.shared.b16 {%0,%1,%2,%3}, [%4];"
                 : "=r"(r[0]), "=r"(r[1]), "=r"(r[2]), "=r"(r[3]) : "r"(a));
}
// fp16 mma, f32 accumulate. Non-volatile: pure register op.
__device__ __forceinline__ void mma16(float c[4], const uint32_t a[4], uint32_t b0, uint32_t b1) {
    asm("mma.sync.aligned.m16n8k16.row.col.f32.f16.f16.f32 "
        "{%0,%1,%2,%3}, {%4,%5,%6,%7}, {%8,%9}, {%0,%1,%2,%3};"
        : "+f"(c[0]), "+f"(c[1]), "+f"(c[2]), "+f"(c[3])
        : "r"(a[0]), "r"(a[1]), "r"(a[2]), "r"(a[3]), "r"(b0), "r"(b1));
}

__device__ __forceinline__ void cpa16(uint32_t d, const void* s) {
    asm volatile("cp.async.cg.shared.global [%0], [%1], 16;" :: "r"(d), "l"(s) : "memory");
}
#define CPA_COMMIT() asm volatile("cp.async.commit_group;" ::: "memory")
#define CPA_WAIT1()  asm volatile("cp.async.wait_group 1;" ::: "memory")
#define CPA_WAIT0()  asm volatile("cp.async.wait_group 0;" ::: "memory")

#define LOG2E_F 1.4426950408889634f

// ---------------------------------------------------------------------------
// conv_kernel: fp32 -> fp16 conversions.
// z=0: x -> g_xh (single term). z=1: pos_emb -> g_peh/g_pel (hi/lo).
// z=2..6: Wq,Wk,Wv,Wpos,Wout -> g_wh (single fp16).
// ---------------------------------------------------------------------------
__global__ __launch_bounds__(256) void conv_kernel(
    const float* __restrict__ x, const float* __restrict__ pe,
    const float* __restrict__ Wq, const float* __restrict__ Wk,
    const float* __restrict__ Wv, const float* __restrict__ Wpos,
    const float* __restrict__ Wout)
{
    int z = blockIdx.y;
    int stride = gridDim.x * 256;
    if (z == 0) {
        const float4* src = (const float4*)x;
        uint2* dh = (uint2*)g_xh_;
        for (int i = blockIdx.x * 256 + threadIdx.x; i < 1048576; i += stride) {
            float4 v = src[i];
            dh[i] = make_uint2(pack2h(v.x, v.y), pack2h(v.z, v.w));
        }
    } else if (z == 1) {
        const float4* src = (const float4*)pe;
        uint2* dh = (uint2*)g_peh_;
        uint2* dl = (uint2*)g_pel_;
        for (int i = blockIdx.x * 256 + threadIdx.x; i < 262144; i += stride) {
            float4 v = src[i];
            uint32_t h0 = pack2h(v.x, v.y);
            uint32_t h1 = pack2h(v.z, v.w);
            float2 f0 = __half22float2(*reinterpret_cast<__half2*>(&h0));
            float2 f1 = __half22float2(*reinterpret_cast<__half2*>(&h1));
            dh[i] = make_uint2(h0, h1);
            dl[i] = make_uint2(pack2h(v.x - f0.x, v.y - f0.y), pack2h(v.z - f1.x, v.w - f1.y));
        }
    } else {
        int widx = z - 2;
        const float* Wsel = (widx == 0) ? Wq : (widx == 1) ? Wk : (widx == 2) ? Wv
                          : (widx == 3) ? Wpos : Wout;
        const float4* src = (const float4*)Wsel;
        uint2* dh = (uint2*)g_wh_ + (size_t)widx * 65536;
        for (int i = blockIdx.x * 256 + threadIdx.x; i < 65536; i += stride) {
            float4 v = src[i];
            dh[i] = make_uint2(pack2h(v.x, v.y), pack2h(v.z, v.w));
        }
    }
}

// ---------------------------------------------------------------------------
// fp16 tensor-core projection GEMM (R12-proven): C[m,n] = (Ah[+Al])[m,:] . W[n,:]
// CTA: 128 rows x 64 cols, 8 warps. K=512 in 8 chunks of 64, double-buffered.
// mode (blockIdx.z if arg<0): 0=Q, 1=K, 2=V, 3=P, 4=OUT — scatter epilogues.
// Only mode 3 (P) uses the 2-term A split.
// ---------------------------------------------------------------------------
#define KSTR2 144         // 64 f16 + 16B pad
#define SM_AH 0
#define SM_AL 18432
#define SM_B  36864
#define GSTAGE 46080
#define GEMM_SMEM (2*GSTAGE)   // 92160 -> 2 CTAs/SM

__device__ __forceinline__ void copy_gtile(
    uint32_t stb, const uint4* Ah, const uint4* Al, const uint4* Wb,
    int m0, int n0, int k08, int tid, bool two_term)
{
#pragma unroll
    for (int i = 0; i < 4; i++) {
        int idx = tid + i * 256;          // 1024: 128 rows x 8 uint4
        int r = idx >> 3, c = idx & 7;
        size_t so = (size_t)(m0 + r) * 64 + k08 + c;
        cpa16(stb + SM_AH + r * KSTR2 + c * 16, Ah + so);
        if (two_term) cpa16(stb + SM_AL + r * KSTR2 + c * 16, Al + so);
    }
#pragma unroll
    for (int i = 0; i < 2; i++) {
        int idx = tid + i * 256;          // 512: 64 rows x 8 uint4
        int r = idx >> 3, c = idx & 7;
        cpa16(stb + SM_B + r * KSTR2 + c * 16, Wb + (size_t)(n0 + r) * 64 + k08 + c);
    }
}

__global__ __launch_bounds__(256, 2) void proj_kernel(
    int mode_arg, float* __restrict__ out,
    const float* __restrict__ bq, const float* __restrict__ bk,
    const float* __restrict__ bv, const float* __restrict__ bout,
    const float* __restrict__ pbu, const float* __restrict__ pbv)
{
    extern __shared__ char sm[];
    uint32_t sb = cvta_s(sm);

    int tid = threadIdx.x;
    int w = tid >> 5, l = tid & 31;
    int mode = (mode_arg < 0) ? (int)blockIdx.z : mode_arg;
    int m0 = blockIdx.y << 7, n0 = blockIdx.x << 6;
    if (mode == 3 && m0 >= 2048) return;   // P has only 2048 rows (uniform exit, pre-sync)

    bool two_term = (mode == 3);
    const uint4* Ah = (mode <= 2) ? g_xh_ : (mode == 3) ? g_peh_ : g_aoh_;
    const uint4* Al = g_pel_;              // only used when mode==3
    int widx = (mode <= 2) ? mode : ((mode == 3) ? 3 : 4);
    const uint4* Wb = g_wh_ + (size_t)widx * 32768;

    // prologue: chunks 0,1
    copy_gtile(sb, Ah, Al, Wb, m0, n0, 0, tid, two_term);  CPA_COMMIT();
    copy_gtile(sb + GSTAGE, Ah, Al, Wb, m0, n0, 8, tid, two_term);  CPA_COMMIT();

    float acc[4][2][4];
#pragma unroll
    for (int a = 0; a < 4; a++)
#pragma unroll
        for (int bq2 = 0; bq2 < 2; bq2++)
#pragma unroll
            for (int c = 0; c < 4; c++) acc[a][bq2][c] = 0.f;

    uint32_t rowa_rel = (16 * w + (l & 15)) * KSTR2 + (l >> 4) * 16;
    uint32_t kB_rel   = (l & 7) * KSTR2 + (l >> 3) * 16;

    for (int ch = 0; ch < 8; ch++) {
        if (ch < 6) { CPA_WAIT1(); } else { CPA_WAIT0(); }
        __syncthreads();

        uint32_t stb = sb + (ch & 1) * GSTAGE;

        uint32_t Afh[4][4], Afl[4][4];
#pragma unroll
        for (int ks = 0; ks < 4; ks++) {
            ldsm4(Afh[ks], stb + SM_AH + rowa_rel + ks * 32);
            if (two_term) ldsm4(Afl[ks], stb + SM_AL + rowa_rel + ks * 32);
        }
#pragma unroll
        for (int nb = 0; nb < 4; nb++) {
            uint32_t r0 = stb + SM_B + (16 * nb) * KSTR2 + kB_rel;
            uint32_t r1 = r0 + 8 * KSTR2;
#pragma unroll
            for (int j = 0; j < 2; j++) {
                uint32_t B0[4], B1[4];
                ldsm4(B0, r0 + j * 64);
                ldsm4(B1, r1 + j * 64);
                mma16(acc[nb][0], Afh[2*j],   B0[0], B0[1]);
                mma16(acc[nb][1], Afh[2*j],   B1[0], B1[1]);
                mma16(acc[nb][0], Afh[2*j+1], B0[2], B0[3]);
                mma16(acc[nb][1], Afh[2*j+1], B1[2], B1[3]);
                if (two_term) {
                    mma16(acc[nb][0], Afl[2*j],   B0[0], B0[1]);
                    mma16(acc[nb][1], Afl[2*j],   B1[0], B1[1]);
                    mma16(acc[nb][0], Afl[2*j+1], B0[2], B0[3]);
                    mma16(acc[nb][1], Afl[2*j+1], B1[2], B1[3]);
                }
            }
        }
        __syncthreads();
        if (ch + 2 < 8) {
            copy_gtile(sb + (ch & 1) * GSTAGE, Ah, Al, Wb, m0, n0, (ch + 2) * 8, tid, two_term);
            CPA_COMMIT();
        }
    }

    // ---- epilogue: scatter per mode ----
    int row0 = 16 * w + (l >> 2);
    int m = m0 + row0;          // rows m and m+8
    int colb = (l & 3) << 1;

#pragma unroll
    for (int nb = 0; nb < 4; nb++) {
#pragma unroll
        for (int half = 0; half < 2; half++) {
            int n = n0 + nb * 16 + half * 8 + colb;   // n, n+1
            float c0 = acc[nb][half][0], c1 = acc[nb][half][1];
            float c2 = acc[nb][half][2], c3 = acc[nb][half][3];
            int h = n >> 6, dd = n & 63;

            if (mode == 0) {
                float b0 = bq[n], b1 = bq[n + 1];
                float u0 = pbu[n], u1 = pbu[n + 1];
                float v0 = pbv[n], v1 = pbv[n + 1];
                int bb = m >> 11, t = m & (TT - 1);
                size_t base = ((size_t)(bb * HH + h) * TT + t) * 128 + dd;
                *(uint32_t*)(G_QH + base)      = pack2h((c0+b0+u0)*0.125f, (c1+b1+u1)*0.125f);
                *(uint32_t*)(G_QH + base + 64) = pack2h((c0+b0+v0)*0.125f, (c1+b1+v1)*0.125f);
                size_t base2 = base + (size_t)8 * 128;
                *(uint32_t*)(G_QH + base2)      = pack2h((c2+b0+u0)*0.125f, (c3+b1+u1)*0.125f);
                *(uint32_t*)(G_QH + base2 + 64) = pack2h((c2+b0+v0)*0.125f, (c3+b1+v1)*0.125f);
            } else if (mode == 1) {
                float b0 = bk[n], b1 = bk[n + 1];
                int bb = m >> 11, t = m & (TT - 1);
                size_t base = ((size_t)(bb * HH + h) * TT + t) * 128 + dd;
                *(uint32_t*)(G_KH + base) = pack2h(c0 + b0, c1 + b1);
                *(uint32_t*)(G_KH + base + (size_t)8 * 128) = pack2h(c2 + b0, c3 + b1);
            } else if (mode == 2) {
                float b0 = bv[n], b1 = bv[n + 1];
                int bb = m >> 11, t = m & (TT - 1);
                size_t base = ((size_t)(bb * HH + h) * TT + t) * 64 + dd;
                *(uint32_t*)(G_VH + base) = pack2h(c0 + b0, c1 + b1);
                *(uint32_t*)(G_VH + base + (size_t)8 * 64) = pack2h(c2 + b0, c3 + b1);
            } else if (mode == 3) {
                int t = m;   // 0..2047
                uint32_t p0 = pack2h(c0, c1);
                uint32_t p1 = pack2h(c2, c3);
#pragma unroll
                for (int bb = 0; bb < BB; bb++) {
                    size_t base = ((size_t)(bb * HH + h) * TT + t) * 128 + 64 + dd;
                    *(uint32_t*)(G_KH + base) = p0;
                    *(uint32_t*)(G_KH + base + (size_t)8 * 128) = p1;
                }
            } else {
                float b0 = bout[n], b1 = bout[n + 1];
                *(float2*)(out + (size_t)m * FF + n) = make_float2(c0 + b0, c1 + b1);
                *(float2*)(out + (size_t)(m + 8) * FF + n) = make_float2(c2 + b0, c3 + b1);
            }
        }
    }
}

// ---------------------------------------------------------------------------
// Single-fp16 mma.sync flash attention, ONLINE softmax, 2 CTAs/SM.
// 128-key tiles, double-buffered cp.async. Key-split z in [0,4). (R9-proven)
// R17: O partials written as fp16 (halves po traffic).
// ---------------------------------------------------------------------------
#define KSTR 272     // K/Q smem row stride bytes (128 f16 + 16B pad)
#define VSTR 144     // V smem row stride bytes (64 f16 + 16B pad)
#define SM_K 0
#define SM_V 34816
#define STAGE 53248
#define FLASH_SMEM (2*STAGE)   // 106496 -> 2 CTAs/SM

__device__ __forceinline__ void copy_tile_async(uint32_t stb, int bh, int s0, int tid) {
    const uint4* kh = g_kh_ + ((size_t)bh * TT + s0) * 16;
#pragma unroll
    for (int i = 0; i < 8; i++) {
        int idx = tid + i * 256;
        int r = idx >> 4, c = idx & 15;
        cpa16(stb + SM_K + r * KSTR + c * 16, kh + r * 16 + c);
    }
    const uint4* vh = g_vh_ + ((size_t)bh * TT + s0) * 8;
#pragma unroll
    for (int i = 0; i < 4; i++) {
        int idx = tid + i * 256;
        int r = idx >> 3, c = idx & 7;
        cpa16(stb + SM_V + r * VSTR + c * 16, vh + r * 8 + c);
    }
}

__global__ __launch_bounds__(256, 2) void flash_kernel()
{
    extern __shared__ char sm[];
    uint32_t sb = cvta_s(sm);

    int tid = threadIdx.x;
    int w = tid >> 5, l = tid & 31;
    int bh = blockIdx.y;
    int b = bh >> 3, h = bh & 7;
    int t0 = blockIdx.x << 7;
    int z  = blockIdx.z;
    int kbase = z << 9;

    {
        uint32_t qb = sb + STAGE;
        const uint4* qh = g_qh_ + ((size_t)bh * TT + t0) * 16;
#pragma unroll
        for (int i = 0; i < 8; i++) {
            int idx = tid + i * 256;
            int r = idx >> 4, c = idx & 15;
            cpa16(qb + r * KSTR + c * 16, qh + r * 16 + c);
        }
        CPA_COMMIT();
        copy_tile_async(sb, bh, kbase, tid);
        CPA_COMMIT();
    }
    CPA_WAIT1();
    __syncthreads();

    uint32_t Qf[8][4];
    {
        uint32_t rowa = sb + STAGE + (16 * w + (l & 15)) * KSTR + (l >> 4) * 16;
#pragma unroll
        for (int ks = 0; ks < 8; ks++) ldsm4(Qf[ks], rowa + ks * 32);
    }

    float O[8][4];
#pragma unroll
    for (int i = 0; i < 8; i++)
#pragma unroll
        for (int j = 0; j < 4; j++) O[i][j] = 0.f;
    float l_0 = 0.f, l_1 = 0.f;
    float m_0 = -1e30f, m_1 = -1e30f;

    uint32_t kB_rel = (l & 7) * KSTR + (l >> 3) * 16;
    uint32_t vB_rel = ((l & 7) + ((l >> 3) & 1) * 8) * VSTR + (l >> 4) * 16;

    for (int it = 0; it < 4; ++it) {
        __syncthreads();
        if (it < 3) {
            copy_tile_async(sb + ((it + 1) & 1) * STAGE, bh, kbase + ((it + 1) << 7), tid);
            CPA_COMMIT();
            CPA_WAIT1();
        } else {
            CPA_WAIT0();
        }
        __syncthreads();

        uint32_t stb = sb + (it & 1) * STAGE;
        uint32_t kB_lane = stb + kB_rel;
        uint32_t vB_lane = stb + vB_rel;

#pragma unroll
        for (int kb = 0; kb < 8; kb++) {
            float S0A[4] = {0.f,0.f,0.f,0.f}, S0B[4] = {0.f,0.f,0.f,0.f};
            float S1A[4] = {0.f,0.f,0.f,0.f}, S1B[4] = {0.f,0.f,0.f,0.f};
            uint32_t r0a = kB_lane + SM_K + (16 * kb) * KSTR;
            uint32_t r1a = r0a + 8 * KSTR;
#pragma unroll
            for (int j = 0; j < 4; j++) {
                uint32_t B0[4], B1[4];
                ldsm4(B0, r0a + j * 64);
                ldsm4(B1, r1a + j * 64);
                mma16(S0A, Qf[2*j],   B0[0], B0[1]);
                mma16(S1A, Qf[2*j],   B1[0], B1[1]);
                mma16(S0B, Qf[2*j+1], B0[2], B0[3]);
                mma16(S1B, Qf[2*j+1], B1[2], B1[3]);
            }

            uint32_t va = vB_lane + SM_V + (16 * kb) * VSTR;
            uint32_t V0[4], V1[4], V2[4], V3[4];
            ldsm4t(V0, va);
            ldsm4t(V1, va + 32);
            ldsm4t(V2, va + 64);
            ldsm4t(V3, va + 96);

            float s00 = S0A[0]+S0B[0], s01 = S0A[1]+S0B[1];
            float s02 = S0A[2]+S0B[2], s03 = S0A[3]+S0B[3];
            float s10 = S1A[0]+S1B[0], s11 = S1A[1]+S1B[1];
            float s12 = S1A[2]+S1B[2], s13 = S1A[3]+S1B[3];

            float mx0f = fmaxf(fmaxf(s00, s01), fmaxf(s10, s11));
            float mx1f = fmaxf(fmaxf(s02, s03), fmaxf(s12, s13));
            uint32_t pk = pack2h(mx0f, mx1f);
            {
                uint32_t o1 = __shfl_xor_sync(0xffffffffu, pk, 1);
                __half2 a = *reinterpret_cast<__half2*>(&pk);
                __half2 c = __hmax2(a, *reinterpret_cast<__half2*>(&o1));
                pk = *reinterpret_cast<uint32_t*>(&c);
                uint32_t o2 = __shfl_xor_sync(0xffffffffu, pk, 2);
                __half2 d = __hmax2(*reinterpret_cast<__half2*>(&pk),
                                    *reinterpret_cast<__half2*>(&o2));
                pk = *reinterpret_cast<uint32_t*>(&d);
            }
            float2 mxf = __half22float2(*reinterpret_cast<__half2*>(&pk));
            float mn0 = fmaxf(m_0, mxf.x), mn1 = fmaxf(m_1, mxf.y);
            bool nochg = __all_sync(0xffffffffu, (mn0 == m_0) && (mn1 == m_1));

            float p00 = ex2f((s00 - mn0) * LOG2E_F);
            float p01 = ex2f((s01 - mn0) * LOG2E_F);
            float p10 = ex2f((s10 - mn0) * LOG2E_F);
            float p11 = ex2f((s11 - mn0) * LOG2E_F);
            float p02 = ex2f((s02 - mn1) * LOG2E_F);
            float p03 = ex2f((s03 - mn1) * LOG2E_F);
            float p12 = ex2f((s12 - mn1) * LOG2E_F);
            float p13 = ex2f((s13 - mn1) * LOG2E_F);
            float sum0 = (p00 + p01) + (p10 + p11);
            float sum1 = (p02 + p03) + (p12 + p13);

            if (nochg) {
                l_0 += sum0;
                l_1 += sum1;
            } else {
                float c0 = ex2f((m_0 - mn0) * LOG2E_F);
                float c1 = ex2f((m_1 - mn1) * LOG2E_F);
                l_0 = l_0 * c0 + sum0;
                l_1 = l_1 * c1 + sum1;
                m_0 = mn0; m_1 = mn1;
#pragma unroll
                for (int nd = 0; nd < 8; nd++) {
                    O[nd][0] *= c0; O[nd][1] *= c0;
                    O[nd][2] *= c1; O[nd][3] *= c1;
                }
            }

            uint32_t P[4];
            P[0] = pack2h(p00, p01);
            P[1] = pack2h(p02, p03);
            P[2] = pack2h(p10, p11);
            P[3] = pack2h(p12, p13);

            mma16(O[0], P, V0[0], V0[1]);
            mma16(O[1], P, V0[2], V0[3]);
            mma16(O[2], P, V1[0], V1[1]);
            mma16(O[3], P, V1[2], V1[3]);
            mma16(O[4], P, V2[0], V2[1]);
            mma16(O[5], P, V2[2], V2[3]);
            mma16(O[6], P, V3[0], V3[1]);
            mma16(O[7], P, V3[2], V3[3]);
        }
    }

    l_0 += __shfl_xor_sync(0xffffffffu, l_0, 1);
    l_0 += __shfl_xor_sync(0xffffffffu, l_0, 2);
    l_1 += __shfl_xor_sync(0xffffffffu, l_1, 1);
    l_1 += __shfl_xor_sync(0xffffffffu, l_1, 2);

    float* ls = g_ls + z * 32 * TT;
    float* lm = g_lm + z * 32 * TT;

    int row0 = t0 + 16 * w + (l >> 2);
    if ((l & 3) == 0) {
        ls[bh * TT + row0] = l_0;      lm[bh * TT + row0] = m_0;
        ls[bh * TT + row0 + 8] = l_1;  lm[bh * TT + row0 + 8] = m_1;
    }

    // ---- write fp16 partials ----
    __half* pobase = ((__half*)g_po16) + (size_t)z * MM * FF;
    size_t e0 = ((size_t)(b * TT + row0)) * FF + (h << 6) + ((l & 3) << 1);
    uint32_t* d0 = (uint32_t*)(pobase + e0);
    uint32_t* d1 = (uint32_t*)(pobase + e0 + (size_t)8 * FF);
#pragma unroll
    for (int nd = 0; nd < 8; nd++) {
        d0[nd * 4] = pack2h(O[nd][0], O[nd][1]);
        d1[nd * 4] = pack2h(O[nd][2], O[nd][3]);
    }
}

// ---------------------------------------------------------------------------
// combine NZ fp16 partials with (m,l) merge -> single fp16 ao (feeds OUT gemm)
// ---------------------------------------------------------------------------
__global__ __launch_bounds__(256) void combine_kernel()
{
    int idx = blockIdx.x * 256 + threadIdx.x;   // 4-element groups over MM*FF
    int m = idx >> 7;
    int c = (idx & 127) << 2;
    int h = c >> 6;
    int b = m >> 11, t = m & (TT - 1);
    int r = (b * HH + h) * TT + t;

    float mz[NZ];
    float M = -1e30f;
#pragma unroll
    for (int zz = 0; zz < NZ; zz++) { mz[zz] = g_lm[zz * 32 * TT + r]; M = fmaxf(M, mz[zz]); }
    float L = 0.f;
    float wz[NZ];
#pragma unroll
    for (int zz = 0; zz < NZ; zz++) {
        wz[zz] = ex2f((mz[zz] - M) * LOG2E_F);
        L += g_ls[zz * 32 * TT + r] * wz[zz];
    }
    float inv = 1.f / L;

    float4 acc = make_float4(0.f, 0.f, 0.f, 0.f);
#pragma unroll
    for (int zz = 0; zz < NZ; zz++) {
        uint2 v = g_po16[(size_t)zz * (MM * FF / 4) + idx];
        float2 a01 = __half22float2(*reinterpret_cast<const __half2*>(&v.x));
        float2 a23 = __half22float2(*reinterpret_cast<const __half2*>(&v.y));
        acc.x += a01.x * wz[zz]; acc.y += a01.y * wz[zz];
        acc.z += a23.x * wz[zz]; acc.w += a23.y * wz[zz];
    }
    ((uint2*)g_aoh_)[idx] = make_uint2(pack2h(acc.x * inv, acc.y * inv),
                                       pack2h(acc.z * inv, acc.w * inv));
}

// ---------------------------------------------------------------------------
extern "C" void kernel_launch(void* const* d_in, const int* in_sizes, int n_in,
                              void* d_out, int out_size)
{
    const float* x    = (const float*)d_in[0];
    const float* pe   = (const float*)d_in[1];
    const float* Wq   = (const float*)d_in[2];
    const float* bq   = (const float*)d_in[3];
    const float* Wk   = (const float*)d_in[4];
    const float* bk   = (const float*)d_in[5];
    const float* Wv   = (const float*)d_in[6];
    const float* bv   = (const float*)d_in[7];
    const float* Wpos = (const float*)d_in[8];
    const float* Wout = (const float*)d_in[9];
    const float* bout = (const float*)d_in[10];
    const float* pbu  = (const float*)d_in[11];
    const float* pbv  = (const float*)d_in[12];
    float* out = (float*)d_out;

    cudaFuncSetAttribute(flash_kernel, cudaFuncAttributeMaxDynamicSharedMemorySize, FLASH_SMEM);
    cudaFuncSetAttribute(proj_kernel, cudaFuncAttributeMaxDynamicSharedMemorySize, GEMM_SMEM);

    dim3 blk(256);
    // #0: fp32 -> fp16 conversions (x, pe hi/lo, 5 weights)
    conv_kernel<<<dim3(512, 7), blk>>>(x, pe, Wq, Wk, Wv, Wpos, Wout);
    // #1: fused QKV + P projections (tensor cores; z=3 = P, masked to y<16)
    proj_kernel<<<dim3(8, 64, 4), blk, GEMM_SMEM>>>(-1, nullptr, bq, bk, bv, bout, pbu, pbv);
    // #2: flash attention
    flash_kernel<<<dim3(TT / 128, BB * HH, NZ), blk, FLASH_SMEM>>>();
    // #3: combine split-K fp16 partials -> fp16 ao
    combine_kernel<<<dim3((MM * FF) / 1024), blk>>>();
    // #4: output projection (tensor cores, single-term A) -> d_out
    proj_kernel<<<dim3(8, 64, 1), blk, GEMM_SMEM>>>(4, out, bq, bk, bv, bout, pbu, pbv);
}